// round 13
// baseline (speedup 1.0000x reference)
#include <cuda_runtime.h>
#include <cuda_fp16.h>

#define N_NODES 100000
#define D 384
#define N_ETYPES 8
#define ROW_CH (D / 8)                 // 48 16B-chunks per fp16 row
#define SLOT_CH (2 * 2 * ROW_CH)       // pair: 2 edges x (u row + v row) = 192 chunks
#define DEPTH 2
#define WARPS 16
#define THREADS 512
#define BLOCKS 304

#define RING_BYTES (WARPS * DEPTH * SLOT_CH * 16)            // 98304
#define SMEM_BYTES (RING_BYTES + N_ETYPES * D * 2)           // + fp16 rel = 104448

// fp16 shadow of the node table (rebuilt every launch; static scratch allowed).
__device__ __align__(16) __half g_h16[(size_t)N_NODES * D];

__device__ __forceinline__ unsigned long long evict_last_policy() {
    unsigned long long p;
    asm("createpolicy.fractional.L2::evict_last.b64 %0, 1.0;\n" : "=l"(p));
    return p;
}
__device__ __forceinline__ void cpa16_el(void* smem_dst, const void* gmem_src,
                                         unsigned long long pol) {
    unsigned s = (unsigned)__cvta_generic_to_shared(smem_dst);
    asm volatile("cp.async.cg.shared.global.L2::cache_hint [%0], [%1], 16, %2;\n"
                 :: "r"(s), "l"(gmem_src), "l"(pol) : "memory");
}
__device__ __forceinline__ void cpa_commit() {
    asm volatile("cp.async.commit_group;\n" ::: "memory");
}
__device__ __forceinline__ void cpa_wait() {
    asm volatile("cp.async.wait_group %0;\n" :: "n"(DEPTH - 1) : "memory");
}
__device__ __forceinline__ void st128_el(void* ptr, uint4 val,
                                         unsigned long long pol) {
    asm volatile("st.global.L2::cache_hint.v4.b32 [%0], {%1,%2,%3,%4}, %5;\n"
                 :: "l"(ptr), "r"(val.x), "r"(val.y), "r"(val.z), "r"(val.w),
                    "l"(pol) : "memory");
}
__device__ __forceinline__ void gdc_launch_dependents() {
    asm volatile("griddepcontrol.launch_dependents;" ::: "memory");
}
__device__ __forceinline__ void gdc_wait() {
    asm volatile("griddepcontrol.wait;" ::: "memory");
}

__device__ __forceinline__ uint4 cvt8(float4 a, float4 b) {
    __half2 h0 = __floats2half2_rn(a.x, a.y);
    __half2 h1 = __floats2half2_rn(a.z, a.w);
    __half2 h2 = __floats2half2_rn(b.x, b.y);
    __half2 h3 = __floats2half2_rn(b.z, b.w);
    uint4 o;
    o.x = *(unsigned*)&h0; o.y = *(unsigned*)&h1;
    o.z = *(unsigned*)&h2; o.w = *(unsigned*)&h3;
    return o;
}

// ── Kernel 1: fp32 -> fp16 streaming convert, 64B-out per thread ──
// 4 front-batched evict-first loads (MLP=4 per thread), 2 evict-last stores.
__global__ __launch_bounds__(256)
void convert_kernel(const float* __restrict__ h) {
    size_t i = (size_t)blockIdx.x * blockDim.x + threadIdx.x;   // 64B-out chunk id
    size_t total = (size_t)N_NODES * D / 16;                    // 2.4M
    if (i < total) {
        unsigned long long pol = evict_last_policy();
        const float4* src = (const float4*)h;
        float4 a0 = __ldcs(src + 4 * i);
        float4 a1 = __ldcs(src + 4 * i + 1);
        float4 a2 = __ldcs(src + 4 * i + 2);
        float4 a3 = __ldcs(src + 4 * i + 3);
        st128_el((uint4*)g_h16 + 2 * i,     cvt8(a0, a1), pol);
        st128_el((uint4*)g_h16 + 2 * i + 1, cvt8(a2, a3), pol);
    }
    gdc_launch_dependents();   // let the gather's prologue start
}

// ── Kernel 2: cp.async-ring gather + DistMult, fp16 rel in smem; PDL entry ──
__global__ __launch_bounds__(THREADS, 2)
void gather_kernel(const int* __restrict__ u,
                   const int* __restrict__ v,
                   const int* __restrict__ etype,
                   const float* __restrict__ rel,
                   float* __restrict__ out,
                   int n_edges) {
    extern __shared__ char smem[];
    uint4*  buf     = (uint4*)smem;                       // [WARPS][DEPTH][192]
    __half* s_rel16 = (__half*)(smem + RING_BYTES);       // 8x384 fp16

    // Table-independent prologue BEFORE the dependency wait (overlaps convert tail).
    for (int i = threadIdx.x; i < N_ETYPES * D / 2; i += THREADS) {
        float2 rf = ((const float2*)rel)[i];
        ((__half2*)s_rel16)[i] = __floats2half2_rn(rf.x, rf.y);
    }
    __syncthreads();

    unsigned long long pol = evict_last_policy();

    int wid  = threadIdx.x >> 5;
    int lane = threadIdx.x & 31;
    int hh   = lane >> 4;          // which edge of the pair
    int sub  = lane & 15;          // lane within the 16-lane edge group
    uint4* wbuf = buf + wid * (DEPTH * SLOT_CH);

    int total_warps = BLOCKS * WARPS;
    int n_pairs = (n_edges + 1) / 2;
    int gw    = blockIdx.x * WARPS + wid;
    int K     = (n_pairs + total_warps - 1) / total_warps;
    int pbase = gw * K;
    int pend  = pbase + K; if (pend > n_pairs) pend = n_pairs;

    // Prefetch prologue indices (table-independent) before the wait.
    int pui[DEPTH], pvi[DEPTH];
    #pragma unroll
    for (int s = 0; s < DEPTH; s++) {
        int p = pbase + s;
        int e  = 2 * p + hh;
        int ec = (p < pend && e < n_edges) ? e : 0;
        pui[s] = __ldg(u + ec);
        pvi[s] = __ldg(v + ec);
    }

    gdc_wait();   // convert's table stores now guaranteed visible

    // ── Prologue: fill DEPTH stages ──
    #pragma unroll
    for (int s = 0; s < DEPTH; s++) {
        int p = pbase + s;
        if (p < pend) {
            const uint4* hu = (const uint4*)(g_h16 + (size_t)pui[s] * D);
            const uint4* hv = (const uint4*)(g_h16 + (size_t)pvi[s] * D);
            uint4* slot = wbuf + s * SLOT_CH + hh * (2 * ROW_CH);
            #pragma unroll
            for (int k = 0; k < 3; k++) {
                cpa16_el(slot + sub + 16 * k,          hu + sub + 16 * k, pol);
                cpa16_el(slot + ROW_CH + sub + 16 * k, hv + sub + 16 * k, pol);
            }
        }
        cpa_commit();
    }

    // ── Steady state ──
    int s = 0;
    for (int p = pbase; p < pend; p++) {
        cpa_wait();   // this lane's own bytes for pair p are complete

        const uint4* slot = wbuf + s * SLOT_CH + hh * (2 * ROW_CH);

        // 1) Pull row data smem -> regs...
        uint4 uu0 = slot[sub];          uint4 vv0 = slot[ROW_CH + sub];
        uint4 uu1 = slot[sub + 16];     uint4 vv1 = slot[ROW_CH + sub + 16];
        uint4 uu2 = slot[sub + 32];     uint4 vv2 = slot[ROW_CH + sub + 32];

        // 2) ...refill immediately so loads overlap the math tail.
        int np = p + DEPTH;
        if (np < pend) {
            int ne  = 2 * np + hh;
            int nec = ne < n_edges ? ne : 0;
            int ui = __ldg(u + nec);
            int vi = __ldg(v + nec);
            const uint4* hu = (const uint4*)(g_h16 + (size_t)ui * D);
            const uint4* hv = (const uint4*)(g_h16 + (size_t)vi * D);
            uint4* wslot = wbuf + s * SLOT_CH + hh * (2 * ROW_CH);
            #pragma unroll
            for (int k = 0; k < 3; k++) {
                cpa16_el(wslot + sub + 16 * k,          hu + sub + 16 * k, pol);
                cpa16_el(wslot + ROW_CH + sub + 16 * k, hv + sub + 16 * k, pol);
            }
        }
        cpa_commit();

        // 3) Math: fp16 products, fp32 accumulate.
        int e  = 2 * p + hh;
        int ec = e < n_edges ? e : 0;
        int ei = __ldg(etype + ec);
        const uint4* rr = (const uint4*)(s_rel16 + ei * D);

        float acc = 0.0f;
        {
            uint4 U[3] = { uu0, uu1, uu2 };
            uint4 V[3] = { vv0, vv1, vv2 };
            #pragma unroll
            for (int k = 0; k < 3; k++) {
                int c = sub + 16 * k;
                uint4 uu = U[k], vv = V[k];
                uint4 rc = rr[c];
                __half2 p0 = __hmul2(*(__half2*)&uu.x, *(__half2*)&vv.x);
                __half2 p1 = __hmul2(*(__half2*)&uu.y, *(__half2*)&vv.y);
                __half2 p2 = __hmul2(*(__half2*)&uu.z, *(__half2*)&vv.z);
                __half2 p3 = __hmul2(*(__half2*)&uu.w, *(__half2*)&vv.w);
                float2 f0 = __half22float2(p0);
                float2 f1 = __half22float2(p1);
                float2 f2 = __half22float2(p2);
                float2 f3 = __half22float2(p3);
                float2 r0 = __half22float2(*(__half2*)&rc.x);
                float2 r1 = __half22float2(*(__half2*)&rc.y);
                float2 r2 = __half22float2(*(__half2*)&rc.z);
                float2 r3 = __half22float2(*(__half2*)&rc.w);
                acc = fmaf(f0.x, r0.x, acc); acc = fmaf(f0.y, r0.y, acc);
                acc = fmaf(f1.x, r1.x, acc); acc = fmaf(f1.y, r1.y, acc);
                acc = fmaf(f2.x, r2.x, acc); acc = fmaf(f2.y, r2.y, acc);
                acc = fmaf(f3.x, r3.x, acc); acc = fmaf(f3.y, r3.y, acc);
            }
        }

        #pragma unroll
        for (int o = 8; o > 0; o >>= 1)
            acc += __shfl_xor_sync(0xffffffffu, acc, o);
        if (sub == 0 && e < n_edges)
            out[e] = 1.0f / (1.0f + __expf(-acc));

        s ^= 1;   // DEPTH == 2
    }
}

extern "C" void kernel_launch(void* const* d_in, const int* in_sizes, int n_in,
                              void* d_out, int out_size) {
    const float* h   = (const float*)d_in[0];
    const int*   u   = (const int*)d_in[1];
    const int*   v   = (const int*)d_in[2];
    const int*   et  = (const int*)d_in[3];
    const float* rel = (const float*)d_in[4];
    float*       out = (float*)d_out;

    int n_edges = in_sizes[1];   // 250000

    size_t conv_threads = (size_t)N_NODES * D / 16;   // 2.4M (64B out each)
    convert_kernel<<<(int)((conv_threads + 255) / 256), 256>>>(h);

    cudaFuncSetAttribute(gather_kernel,
                         cudaFuncAttributeMaxDynamicSharedMemorySize, SMEM_BYTES);

    // PDL: gather launches while convert drains; self-syncs via griddepcontrol.
    cudaLaunchConfig_t cfg = {};
    cfg.gridDim  = dim3(BLOCKS, 1, 1);
    cfg.blockDim = dim3(THREADS, 1, 1);
    cfg.dynamicSmemBytes = SMEM_BYTES;
    cfg.stream = 0;
    cudaLaunchAttribute attrs[1];
    attrs[0].id = cudaLaunchAttributeProgrammaticStreamSerialization;
    attrs[0].val.programmaticStreamSerializationAllowed = 1;
    cfg.attrs = attrs;
    cfg.numAttrs = 1;
    cudaLaunchKernelEx(&cfg, gather_kernel, u, v, et, rel, out, n_edges);
}

// round 14
// speedup vs baseline: 1.0689x; 1.0689x over previous
#include <cuda_runtime.h>
#include <cuda_fp16.h>

#define N_NODES 100000
#define D 384
#define N_ETYPES 8
#define ROW_CH (D / 8)                 // 48 16B-chunks per fp16 row
#define SLOT_CH (2 * 2 * ROW_CH)       // pair: 2 edges x (u row + v row) = 192 chunks
#define DEPTH 2
#define WARPS 16
#define THREADS 512
#define BLOCKS 304

#define RING_BYTES (WARPS * DEPTH * SLOT_CH * 16)            // 98304
#define SMEM_BYTES (RING_BYTES + N_ETYPES * D * 2)           // + fp16 rel = 104448

// fp16 shadow of the node table (rebuilt every launch; static scratch allowed).
__device__ __align__(16) __half g_h16[(size_t)N_NODES * D];

__device__ __forceinline__ unsigned long long evict_last_policy() {
    unsigned long long p;
    asm("createpolicy.fractional.L2::evict_last.b64 %0, 1.0;\n" : "=l"(p));
    return p;
}
__device__ __forceinline__ void cpa16_el(void* smem_dst, const void* gmem_src,
                                         unsigned long long pol) {
    unsigned s = (unsigned)__cvta_generic_to_shared(smem_dst);
    asm volatile("cp.async.cg.shared.global.L2::cache_hint [%0], [%1], 16, %2;\n"
                 :: "r"(s), "l"(gmem_src), "l"(pol) : "memory");
}
__device__ __forceinline__ void cpa_commit() {
    asm volatile("cp.async.commit_group;\n" ::: "memory");
}
__device__ __forceinline__ void cpa_wait() {
    asm volatile("cp.async.wait_group %0;\n" :: "n"(DEPTH - 1) : "memory");
}
__device__ __forceinline__ void st128_el(void* ptr, uint4 val,
                                         unsigned long long pol) {
    asm volatile("st.global.L2::cache_hint.v4.b32 [%0], {%1,%2,%3,%4}, %5;\n"
                 :: "l"(ptr), "r"(val.x), "r"(val.y), "r"(val.z), "r"(val.w),
                    "l"(pol) : "memory");
}
__device__ __forceinline__ void gdc_launch_dependents() {
    asm volatile("griddepcontrol.launch_dependents;" ::: "memory");
}
__device__ __forceinline__ void gdc_wait() {
    asm volatile("griddepcontrol.wait;" ::: "memory");
}

// ── Kernel 1: fp32 -> fp16 streaming convert (R12 shape: 8 floats/thread) ──
// launch_dependents FIRST: dependent gather grid dispatches immediately and
// runs its table-independent prologue concurrently with this kernel's body.
__global__ __launch_bounds__(256)
void convert_kernel(const float* __restrict__ h) {
    gdc_launch_dependents();

    size_t i = (size_t)blockIdx.x * blockDim.x + threadIdx.x;
    size_t total = (size_t)N_NODES * D / 8;
    if (i < total) {
        unsigned long long pol = evict_last_policy();
        const float4* src = (const float4*)h;
        float4 a = __ldcs(src + 2 * i);       // evict-first fp32 stream
        float4 b = __ldcs(src + 2 * i + 1);
        __half2 h0 = __floats2half2_rn(a.x, a.y);
        __half2 h1 = __floats2half2_rn(a.z, a.w);
        __half2 h2 = __floats2half2_rn(b.x, b.y);
        __half2 h3 = __floats2half2_rn(b.z, b.w);
        uint4 o;
        o.x = *(unsigned*)&h0; o.y = *(unsigned*)&h1;
        o.z = *(unsigned*)&h2; o.w = *(unsigned*)&h3;
        st128_el((uint4*)g_h16 + i, o, pol);  // keep table L2-resident
    }
}

// ── Kernel 2: cp.async-ring gather + DistMult, fp16 rel in smem; PDL entry ──
__global__ __launch_bounds__(THREADS, 2)
void gather_kernel(const int* __restrict__ u,
                   const int* __restrict__ v,
                   const int* __restrict__ etype,
                   const float* __restrict__ rel,
                   float* __restrict__ out,
                   int n_edges) {
    extern __shared__ char smem[];
    uint4*  buf     = (uint4*)smem;                       // [WARPS][DEPTH][192]
    __half* s_rel16 = (__half*)(smem + RING_BYTES);       // 8x384 fp16

    // Table-independent prologue BEFORE the dependency wait (overlaps convert).
    for (int i = threadIdx.x; i < N_ETYPES * D / 2; i += THREADS) {
        float2 rf = ((const float2*)rel)[i];
        ((__half2*)s_rel16)[i] = __floats2half2_rn(rf.x, rf.y);
    }
    __syncthreads();

    unsigned long long pol = evict_last_policy();

    int wid  = threadIdx.x >> 5;
    int lane = threadIdx.x & 31;
    int hh   = lane >> 4;          // which edge of the pair
    int sub  = lane & 15;          // lane within the 16-lane edge group
    uint4* wbuf = buf + wid * (DEPTH * SLOT_CH);

    int total_warps = BLOCKS * WARPS;
    int n_pairs = (n_edges + 1) / 2;
    int gw    = blockIdx.x * WARPS + wid;
    int K     = (n_pairs + total_warps - 1) / total_warps;
    int pbase = gw * K;
    int pend  = pbase + K; if (pend > n_pairs) pend = n_pairs;

    // Prefetch prologue indices (table-independent) before the wait.
    int pui[DEPTH], pvi[DEPTH];
    #pragma unroll
    for (int s = 0; s < DEPTH; s++) {
        int p = pbase + s;
        int e  = 2 * p + hh;
        int ec = (p < pend && e < n_edges) ? e : 0;
        pui[s] = __ldg(u + ec);
        pvi[s] = __ldg(v + ec);
    }

    gdc_wait();   // convert grid fully complete; table stores visible

    // ── Prologue: fill DEPTH stages ──
    #pragma unroll
    for (int s = 0; s < DEPTH; s++) {
        int p = pbase + s;
        if (p < pend) {
            const uint4* hu = (const uint4*)(g_h16 + (size_t)pui[s] * D);
            const uint4* hv = (const uint4*)(g_h16 + (size_t)pvi[s] * D);
            uint4* slot = wbuf + s * SLOT_CH + hh * (2 * ROW_CH);
            #pragma unroll
            for (int k = 0; k < 3; k++) {
                cpa16_el(slot + sub + 16 * k,          hu + sub + 16 * k, pol);
                cpa16_el(slot + ROW_CH + sub + 16 * k, hv + sub + 16 * k, pol);
            }
        }
        cpa_commit();
    }

    // ── Steady state ──
    int s = 0;
    for (int p = pbase; p < pend; p++) {
        cpa_wait();   // this lane's own bytes for pair p are complete

        const uint4* slot = wbuf + s * SLOT_CH + hh * (2 * ROW_CH);

        // 1) Pull row data smem -> regs...
        uint4 uu0 = slot[sub];          uint4 vv0 = slot[ROW_CH + sub];
        uint4 uu1 = slot[sub + 16];     uint4 vv1 = slot[ROW_CH + sub + 16];
        uint4 uu2 = slot[sub + 32];     uint4 vv2 = slot[ROW_CH + sub + 32];

        // 2) ...refill immediately so loads overlap the math tail.
        int np = p + DEPTH;
        if (np < pend) {
            int ne  = 2 * np + hh;
            int nec = ne < n_edges ? ne : 0;
            int ui = __ldg(u + nec);
            int vi = __ldg(v + nec);
            const uint4* hu = (const uint4*)(g_h16 + (size_t)ui * D);
            const uint4* hv = (const uint4*)(g_h16 + (size_t)vi * D);
            uint4* wslot = wbuf + s * SLOT_CH + hh * (2 * ROW_CH);
            #pragma unroll
            for (int k = 0; k < 3; k++) {
                cpa16_el(wslot + sub + 16 * k,          hu + sub + 16 * k, pol);
                cpa16_el(wslot + ROW_CH + sub + 16 * k, hv + sub + 16 * k, pol);
            }
        }
        cpa_commit();

        // 3) Math: fp16 products, fp32 accumulate.
        int e  = 2 * p + hh;
        int ec = e < n_edges ? e : 0;
        int ei = __ldg(etype + ec);
        const uint4* rr = (const uint4*)(s_rel16 + ei * D);

        float acc = 0.0f;
        {
            uint4 U[3] = { uu0, uu1, uu2 };
            uint4 V[3] = { vv0, vv1, vv2 };
            #pragma unroll
            for (int k = 0; k < 3; k++) {
                int c = sub + 16 * k;
                uint4 uu = U[k], vv = V[k];
                uint4 rc = rr[c];
                __half2 p0 = __hmul2(*(__half2*)&uu.x, *(__half2*)&vv.x);
                __half2 p1 = __hmul2(*(__half2*)&uu.y, *(__half2*)&vv.y);
                __half2 p2 = __hmul2(*(__half2*)&uu.z, *(__half2*)&vv.z);
                __half2 p3 = __hmul2(*(__half2*)&uu.w, *(__half2*)&vv.w);
                float2 f0 = __half22float2(p0);
                float2 f1 = __half22float2(p1);
                float2 f2 = __half22float2(p2);
                float2 f3 = __half22float2(p3);
                float2 r0 = __half22float2(*(__half2*)&rc.x);
                float2 r1 = __half22float2(*(__half2*)&rc.y);
                float2 r2 = __half22float2(*(__half2*)&rc.z);
                float2 r3 = __half22float2(*(__half2*)&rc.w);
                acc = fmaf(f0.x, r0.x, acc); acc = fmaf(f0.y, r0.y, acc);
                acc = fmaf(f1.x, r1.x, acc); acc = fmaf(f1.y, r1.y, acc);
                acc = fmaf(f2.x, r2.x, acc); acc = fmaf(f2.y, r2.y, acc);
                acc = fmaf(f3.x, r3.x, acc); acc = fmaf(f3.y, r3.y, acc);
            }
        }

        #pragma unroll
        for (int o = 8; o > 0; o >>= 1)
            acc += __shfl_xor_sync(0xffffffffu, acc, o);
        if (sub == 0 && e < n_edges)
            out[e] = 1.0f / (1.0f + __expf(-acc));

        s ^= 1;   // DEPTH == 2
    }
}

extern "C" void kernel_launch(void* const* d_in, const int* in_sizes, int n_in,
                              void* d_out, int out_size) {
    const float* h   = (const float*)d_in[0];
    const int*   u   = (const int*)d_in[1];
    const int*   v   = (const int*)d_in[2];
    const int*   et  = (const int*)d_in[3];
    const float* rel = (const float*)d_in[4];
    float*       out = (float*)d_out;

    int n_edges = in_sizes[1];   // 250000

    size_t conv_threads = (size_t)N_NODES * D / 8;   // 4.8M (R12 shape)
    convert_kernel<<<(int)((conv_threads + 255) / 256), 256>>>(h);

    cudaFuncSetAttribute(gather_kernel,
                         cudaFuncAttributeMaxDynamicSharedMemorySize, SMEM_BYTES);

    // PDL: gather launches while convert runs; self-syncs via griddepcontrol.
    cudaLaunchConfig_t cfg = {};
    cfg.gridDim  = dim3(BLOCKS, 1, 1);
    cfg.blockDim = dim3(THREADS, 1, 1);
    cfg.dynamicSmemBytes = SMEM_BYTES;
    cfg.stream = 0;
    cudaLaunchAttribute attrs[1];
    attrs[0].id = cudaLaunchAttributeProgrammaticStreamSerialization;
    attrs[0].val.programmaticStreamSerializationAllowed = 1;
    cfg.attrs = attrs;
    cfg.numAttrs = 1;
    cudaLaunchKernelEx(&cfg, gather_kernel, u, v, et, rel, out, n_edges);
}